// round 8
// baseline (speedup 1.0000x reference)
#include <cuda_runtime.h>
#include <math.h>

#define N_NODES 100000
#define N_EDGES 3200000
#define F_IN 25
#define F_HID 16
#define F_OUT 2
#define CAP 96   // bucket capacity; deg ~ Poisson(32), P(deg>96) ~ 4e-20

// Scratch (allocation-free rule: __device__ globals)
__device__ int   g_pos[N_NODES];            // bucket cursors (init 96*i)
__device__ int   g_src[N_NODES * CAP];      // source ids bucketed by target
__device__ float g_dinv[N_NODES];
__device__ float g_hs1[N_NODES * F_HID];    // (x@W1) * dinv[i]
__device__ float g_hs2[N_NODES * F_OUT];    // (relu(l1)@W2) * dinv[i]
__device__ int   g_is64;

// ---------------------------------------------------------------------------
// Init cursors + detect edge_index dtype (int64 => odd 32-bit words all zero).
__global__ void k_init(const unsigned int* __restrict__ ei_w) {
    int stride = gridDim.x * blockDim.x;
    int tid = blockIdx.x * blockDim.x + threadIdx.x;
    for (int i = tid; i < N_NODES; i += stride) g_pos[i] = i * CAP;

    if (blockIdx.x == 0) {
        __shared__ int nonzero;
        if (threadIdx.x == 0) nonzero = 0;
        __syncthreads();
        int nz = 0;
        for (int i = threadIdx.x; i < 2048; i += blockDim.x)
            if (ei_w[2 * i + 1] != 0u) nz = 1;
        if (nz) atomicOr(&nonzero, 1);
        __syncthreads();
        if (threadIdx.x == 0) g_is64 = (nonzero == 0) ? 1 : 0;
    }
}

// Bucket fill: 4 edges/thread for atomic MLP. src ids by target node.
__global__ void k_fill(const void* __restrict__ ei) {
    int e0 = 4 * (blockIdx.x * blockDim.x + threadIdx.x);
    if (e0 >= N_EDGES) return;
    int r[4], c[4];
    if (g_is64) {
        const int4* w = (const int4*)ei;  // int64 low/high word pairs
        int4 a = __ldg(&w[e0 / 2]), b = __ldg(&w[e0 / 2 + 1]);
        r[0] = a.x; r[1] = a.z; r[2] = b.x; r[3] = b.z;
        long long cb = (long long)N_EDGES + e0;
        int4 d = __ldg(&w[cb / 2]), f = __ldg(&w[cb / 2 + 1]);
        c[0] = d.x; c[1] = d.z; c[2] = f.x; c[3] = f.z;
    } else {
        const int4* w = (const int4*)ei;
        int4 a = __ldg(&w[e0 / 4]);
        r[0] = a.x; r[1] = a.y; r[2] = a.z; r[3] = a.w;
        int4 d = __ldg(&w[(N_EDGES + e0) / 4]);
        c[0] = d.x; c[1] = d.y; c[2] = d.z; c[3] = d.w;
    }
    int p0 = atomicAdd(&g_pos[c[0]], 1);
    int p1 = atomicAdd(&g_pos[c[1]], 1);
    int p2 = atomicAdd(&g_pos[c[2]], 1);
    int p3 = atomicAdd(&g_pos[c[3]], 1);
    g_src[p0] = r[0];
    g_src[p1] = r[1];
    g_src[p2] = r[2];
    g_src[p3] = r[3];
}

// Layer-1 transform fused with dinv: hs1[i] = (x[i] @ W1) * dinv[i].
__global__ void k_xform1(const float* __restrict__ x, const float* __restrict__ W1) {
    __shared__ float sW1[F_IN * F_HID];
    __shared__ float sx[256 * F_IN];
    for (int i = threadIdx.x; i < F_IN * F_HID; i += blockDim.x)
        sW1[i] = W1[i];

    int base_node = blockIdx.x * 256;
    int nvals = min(256, N_NODES - base_node) * F_IN;
    const float* xblk = x + base_node * F_IN;
    for (int j = threadIdx.x; j < nvals; j += blockDim.x)
        sx[j] = xblk[j];
    __syncthreads();

    int i = base_node + threadIdx.x;
    if (i >= N_NODES) return;

    float deg = (float)(g_pos[i] - i * CAP);
    float di = rsqrtf(deg + 1.0f);  // +1 self loop
    g_dinv[i] = di;

    const float* xi = &sx[threadIdx.x * F_IN];
    float acc[F_HID];
#pragma unroll
    for (int f = 0; f < F_HID; f++) acc[f] = 0.0f;
#pragma unroll
    for (int k = 0; k < F_IN; k++) {
        float xv = xi[k];
#pragma unroll
        for (int f = 0; f < F_HID; f++) acc[f] += xv * sW1[k * F_HID + f];
    }

    float4* out = (float4*)&g_hs1[i * F_HID];
#pragma unroll
    for (int q = 0; q < 4; q++) {
        float4 v;
        v.x = acc[q * 4 + 0] * di;
        v.y = acc[q * 4 + 1] * di;
        v.z = acc[q * 4 + 2] * di;
        v.w = acc[q * 4 + 3] * di;
        out[q] = v;
    }
}

// Layer-1 aggregate: warp per node, 4 lanes per edge (64B row coalesced).
// Bucket indices prefetched in 3 warp-wide loads; gathers fully unrolled,
// predicated, and independent (no index->gather memory dependency).
__global__ void k_agg1(const float* __restrict__ b1, const float* __restrict__ W2) {
    const unsigned FULL = 0xffffffffu;
    int i = (blockIdx.x * blockDim.x + threadIdx.x) >> 5;  // node (grid exact)
    int lane = threadIdx.x & 31;
    int q = lane & 3;        // feature quad
    int slot = lane >> 2;    // edge slot 0..7

    int deg = g_pos[i] - i * CAP;
    const float4* hs = (const float4*)g_hs1;
    const int* bucket = &g_src[i * CAP];

    // whole bucket in registers (CAP=96 = 3 x 32); unused slots never consumed
    int ia = __ldg(&bucket[lane]);
    int ib = __ldg(&bucket[lane + 32]);
    int ic = __ldg(&bucket[lane + 64]);

    float4 acc = make_float4(0.0f, 0.0f, 0.0f, 0.0f);

    // edges 0..31 (always; covers deg<=32 which is ~55% of nodes)
#pragma unroll
    for (int it = 0; it < 4; it++) {
        int e = (it << 3) + slot;
        int r = __shfl_sync(FULL, ia, e);
        if (e < deg) {
            float4 v = __ldg(&hs[r * 4 + q]);
            acc.x += v.x; acc.y += v.y; acc.z += v.z; acc.w += v.w;
        }
    }
    if (deg > 32) {  // warp-uniform branch
#pragma unroll
        for (int it = 4; it < 12; it++) {
            int e = (it << 3) + slot;
            int idx = (it < 8) ? ib : ic;
            int r = __shfl_sync(FULL, idx, e & 31);
            if (e < deg) {
                float4 v = __ldg(&hs[r * 4 + q]);
                acc.x += v.x; acc.y += v.y; acc.z += v.z; acc.w += v.w;
            }
        }
    }

    // reduce across the 8 slots
#pragma unroll
    for (int m = 4; m <= 16; m <<= 1) {
        acc.x += __shfl_xor_sync(FULL, acc.x, m);
        acc.y += __shfl_xor_sync(FULL, acc.y, m);
        acc.z += __shfl_xor_sync(FULL, acc.z, m);
        acc.w += __shfl_xor_sync(FULL, acc.w, m);
    }

    float di = g_dinv[i];
    float4 self = __ldg(&hs[i * 4 + q]);
    float4 bq = __ldg(&((const float4*)b1)[q]);
    float v0 = fmaxf((acc.x + self.x) * di + bq.x, 0.0f);
    float v1 = fmaxf((acc.y + self.y) * di + bq.y, 0.0f);
    float v2 = fmaxf((acc.z + self.z) * di + bq.z, 0.0f);
    float v3 = fmaxf((acc.w + self.w) * di + bq.w, 0.0f);

    int f0 = q * 4;
    float o0 = v0 * __ldg(&W2[(f0 + 0) * 2])     + v1 * __ldg(&W2[(f0 + 1) * 2]) +
               v2 * __ldg(&W2[(f0 + 2) * 2])     + v3 * __ldg(&W2[(f0 + 3) * 2]);
    float o1 = v0 * __ldg(&W2[(f0 + 0) * 2 + 1]) + v1 * __ldg(&W2[(f0 + 1) * 2 + 1]) +
               v2 * __ldg(&W2[(f0 + 2) * 2 + 1]) + v3 * __ldg(&W2[(f0 + 3) * 2 + 1]);

    o0 += __shfl_xor_sync(FULL, o0, 1);
    o0 += __shfl_xor_sync(FULL, o0, 2);
    o1 += __shfl_xor_sync(FULL, o1, 1);
    o1 += __shfl_xor_sync(FULL, o1, 2);

    if (lane == 0) {
        float2 wv;
        wv.x = o0 * di;
        wv.y = o1 * di;
        *(float2*)&g_hs2[i * F_OUT] = wv;
    }
}

// Layer-2 aggregate + finalize + log_softmax: 8 lanes per node.
// Indices prefetched (in-bounds by CAP), gathers predicated + independent.
__global__ void k_agg2(const float* __restrict__ b2, float* __restrict__ out) {
    const unsigned FULL = 0xffffffffu;
    int gid = blockIdx.x * blockDim.x + threadIdx.x;
    int i = gid >> 3;        // grid exact: 100000*8/256 = 3125 blocks
    int sub = gid & 7;

    int deg = g_pos[i] - i * CAP;
    const float2* hs = (const float2*)g_hs2;
    const int* bucket = &g_src[i * CAP];

    // prefetch own indices: sub + 8*it <= 7+88 = 95 < CAP, always in-bounds
    int idxs[12];
#pragma unroll
    for (int it = 0; it < 12; it++)
        idxs[it] = __ldg(&bucket[sub + (it << 3)]);

    float o0 = 0.0f, o1 = 0.0f;
#pragma unroll
    for (int it = 0; it < 12; it++) {
        int e = sub + (it << 3);
        if (e < deg) {
            float2 v = __ldg(&hs[idxs[it]]);
            o0 += v.x;
            o1 += v.y;
        }
    }
    o0 += __shfl_xor_sync(FULL, o0, 1);
    o0 += __shfl_xor_sync(FULL, o0, 2);
    o0 += __shfl_xor_sync(FULL, o0, 4);
    o1 += __shfl_xor_sync(FULL, o1, 1);
    o1 += __shfl_xor_sync(FULL, o1, 2);
    o1 += __shfl_xor_sync(FULL, o1, 4);

    if (sub == 0) {
        float2 self = hs[i];
        float di = g_dinv[i];
        float a0 = (o0 + self.x) * di + __ldg(&b2[0]);
        float a1 = (o1 + self.y) * di + __ldg(&b2[1]);
        float m = fmaxf(a0, a1);
        float lse = m + logf(expf(a0 - m) + expf(a1 - m));
        float2 r2;
        r2.x = a0 - lse;
        r2.y = a1 - lse;
        *(float2*)&out[i * F_OUT] = r2;
    }
}

// ---------------------------------------------------------------------------
extern "C" void kernel_launch(void* const* d_in, const int* in_sizes, int n_in,
                              void* d_out, int out_size) {
    const float* x = (const float*)d_in[0];
    const void* ei = d_in[1];
    const float* W1 = (const float*)d_in[2];
    const float* b1 = (const float*)d_in[3];
    const float* W2 = (const float*)d_in[4];
    const float* b2 = (const float*)d_in[5];
    float* out = (float*)d_out;

    const int TB = 256;
    k_init<<<148, TB>>>((const unsigned int*)ei);
    k_fill<<<(N_EDGES / 4 + TB - 1) / TB, TB>>>(ei);
    k_xform1<<<(N_NODES + TB - 1) / TB, TB>>>(x, W1);
    k_agg1<<<N_NODES * 32 / TB, TB>>>(b1, W2);   // warp per node, exact
    k_agg2<<<N_NODES * 8 / TB, TB>>>(b2, out);   // 8 lanes per node, exact
}

// round 9
// speedup vs baseline: 1.0122x; 1.0122x over previous
#include <cuda_runtime.h>
#include <math.h>

#define N_NODES 100000
#define N_EDGES 3200000
#define F_IN 25
#define F_HID 16
#define F_OUT 2
#define CAP 96   // bucket capacity; deg ~ Poisson(32), P(deg>96) ~ 1e-20

// Scratch (allocation-free rule: __device__ globals)
__device__ int   g_pos[N_NODES];            // bucket cursors (init 96*i)
__device__ int   g_src[N_NODES * CAP];      // source ids bucketed by target
__device__ float g_dinv[N_NODES];
__device__ float g_hs1[N_NODES * F_HID];    // (x@W1) * dinv[i]
__device__ float g_hs2[N_NODES * F_OUT];    // (relu(l1)@W2) * dinv[i]
__device__ int   g_is64;

// ---------------------------------------------------------------------------
// Init cursors + detect edge_index dtype (int64 => odd 32-bit words all zero).
__global__ void k_init(const unsigned int* __restrict__ ei_w) {
    int stride = gridDim.x * blockDim.x;
    int tid = blockIdx.x * blockDim.x + threadIdx.x;
    for (int i = tid; i < N_NODES; i += stride) g_pos[i] = i * CAP;

    if (blockIdx.x == 0) {
        __shared__ int nonzero;
        if (threadIdx.x == 0) nonzero = 0;
        __syncthreads();
        int nz = 0;
        for (int i = threadIdx.x; i < 2048; i += blockDim.x)
            if (ei_w[2 * i + 1] != 0u) nz = 1;
        if (nz) atomicOr(&nonzero, 1);
        __syncthreads();
        if (threadIdx.x == 0) g_is64 = (nonzero == 0) ? 1 : 0;
    }
}

// Bucket fill: 8 edges/thread for atomic/store MLP.
__global__ void k_fill(const void* __restrict__ ei) {
    int e0 = 8 * (blockIdx.x * blockDim.x + threadIdx.x);
    if (e0 >= N_EDGES) return;
    int r[8], c[8];
    if (g_is64) {
        const int4* w = (const int4*)ei;  // int64 low/high word pairs
#pragma unroll
        for (int k = 0; k < 4; k++) {
            int4 a = __ldg(&w[e0 / 2 + k]);
            r[2 * k] = a.x; r[2 * k + 1] = a.z;
        }
        long long cb = (long long)N_EDGES + e0;
#pragma unroll
        for (int k = 0; k < 4; k++) {
            int4 a = __ldg(&w[cb / 2 + k]);
            c[2 * k] = a.x; c[2 * k + 1] = a.z;
        }
    } else {
        const int4* w = (const int4*)ei;
#pragma unroll
        for (int k = 0; k < 2; k++) {
            int4 a = __ldg(&w[e0 / 4 + k]);
            r[4 * k] = a.x; r[4 * k + 1] = a.y; r[4 * k + 2] = a.z; r[4 * k + 3] = a.w;
        }
#pragma unroll
        for (int k = 0; k < 2; k++) {
            int4 a = __ldg(&w[(N_EDGES + e0) / 4 + k]);
            c[4 * k] = a.x; c[4 * k + 1] = a.y; c[4 * k + 2] = a.z; c[4 * k + 3] = a.w;
        }
    }
    int p[8];
#pragma unroll
    for (int k = 0; k < 8; k++) p[k] = atomicAdd(&g_pos[c[k]], 1);
#pragma unroll
    for (int k = 0; k < 8; k++) g_src[p[k]] = r[k];
}

// Layer-1 transform fused with dinv: hs1[i] = (x[i] @ W1) * dinv[i].
__global__ void k_xform1(const float* __restrict__ x, const float* __restrict__ W1) {
    __shared__ float sW1[F_IN * F_HID];
    __shared__ float sx[256 * F_IN];
    for (int i = threadIdx.x; i < F_IN * F_HID; i += blockDim.x)
        sW1[i] = W1[i];

    int base_node = blockIdx.x * 256;
    int nvals = min(256, N_NODES - base_node) * F_IN;
    const float* xblk = x + base_node * F_IN;
    for (int j = threadIdx.x; j < nvals; j += blockDim.x)
        sx[j] = xblk[j];
    __syncthreads();

    int i = base_node + threadIdx.x;
    if (i >= N_NODES) return;

    float deg = (float)(g_pos[i] - i * CAP);
    float di = rsqrtf(deg + 1.0f);  // +1 self loop
    g_dinv[i] = di;

    const float* xi = &sx[threadIdx.x * F_IN];
    float acc[F_HID];
#pragma unroll
    for (int f = 0; f < F_HID; f++) acc[f] = 0.0f;
#pragma unroll
    for (int k = 0; k < F_IN; k++) {
        float xv = xi[k];
#pragma unroll
        for (int f = 0; f < F_HID; f++) acc[f] += xv * sW1[k * F_HID + f];
    }

    float4* out = (float4*)&g_hs1[i * F_HID];
#pragma unroll
    for (int q = 0; q < 4; q++) {
        float4 v;
        v.x = acc[q * 4 + 0] * di;
        v.y = acc[q * 4 + 1] * di;
        v.z = acc[q * 4 + 2] * di;
        v.w = acc[q * 4 + 3] * di;
        out[q] = v;
    }
}

// Layer-1 aggregate: warp per node, 4 lanes per edge (64B row coalesced).
// Bucket indices prefetched warp-wide; tiered unroll (deg<=32 / <=64 / <=96).
__global__ void k_agg1(const float* __restrict__ b1, const float* __restrict__ W2) {
    const unsigned FULL = 0xffffffffu;
    int i = (blockIdx.x * blockDim.x + threadIdx.x) >> 5;  // node (grid exact)
    int lane = threadIdx.x & 31;
    int q = lane & 3;        // feature quad
    int slot = lane >> 2;    // edge slot 0..7

    int deg = g_pos[i] - i * CAP;
    const float4* hs = (const float4*)g_hs1;
    const int* bucket = &g_src[i * CAP];

    int ia = __ldg(&bucket[lane]);
    float4 acc = make_float4(0.0f, 0.0f, 0.0f, 0.0f);

    // tier 0: edges 0..31 (always; covers deg<=32, ~55% of nodes)
#pragma unroll
    for (int it = 0; it < 4; it++) {
        int e = (it << 3) + slot;
        int r = __shfl_sync(FULL, ia, e);
        if (e < deg) {
            float4 v = __ldg(&hs[r * 4 + q]);
            acc.x += v.x; acc.y += v.y; acc.z += v.z; acc.w += v.w;
        }
    }
    if (deg > 32) {  // tier 1: edges 32..63 (warp-uniform)
        int ib = __ldg(&bucket[lane + 32]);
#pragma unroll
        for (int it = 4; it < 8; it++) {
            int e = (it << 3) + slot;
            int r = __shfl_sync(FULL, ib, e & 31);
            if (e < deg) {
                float4 v = __ldg(&hs[r * 4 + q]);
                acc.x += v.x; acc.y += v.y; acc.z += v.z; acc.w += v.w;
            }
        }
        if (deg > 64) {  // tier 2: edges 64..95
            int ic = __ldg(&bucket[lane + 64]);
#pragma unroll
            for (int it = 8; it < 12; it++) {
                int e = (it << 3) + slot;
                int r = __shfl_sync(FULL, ic, e & 31);
                if (e < deg) {
                    float4 v = __ldg(&hs[r * 4 + q]);
                    acc.x += v.x; acc.y += v.y; acc.z += v.z; acc.w += v.w;
                }
            }
        }
    }

    // reduce across the 8 slots
#pragma unroll
    for (int m = 4; m <= 16; m <<= 1) {
        acc.x += __shfl_xor_sync(FULL, acc.x, m);
        acc.y += __shfl_xor_sync(FULL, acc.y, m);
        acc.z += __shfl_xor_sync(FULL, acc.z, m);
        acc.w += __shfl_xor_sync(FULL, acc.w, m);
    }

    float di = g_dinv[i];
    float4 self = __ldg(&hs[i * 4 + q]);
    float4 bq = __ldg(&((const float4*)b1)[q]);
    float v0 = fmaxf((acc.x + self.x) * di + bq.x, 0.0f);
    float v1 = fmaxf((acc.y + self.y) * di + bq.y, 0.0f);
    float v2 = fmaxf((acc.z + self.z) * di + bq.z, 0.0f);
    float v3 = fmaxf((acc.w + self.w) * di + bq.w, 0.0f);

    int f0 = q * 4;
    float o0 = v0 * __ldg(&W2[(f0 + 0) * 2])     + v1 * __ldg(&W2[(f0 + 1) * 2]) +
               v2 * __ldg(&W2[(f0 + 2) * 2])     + v3 * __ldg(&W2[(f0 + 3) * 2]);
    float o1 = v0 * __ldg(&W2[(f0 + 0) * 2 + 1]) + v1 * __ldg(&W2[(f0 + 1) * 2 + 1]) +
               v2 * __ldg(&W2[(f0 + 2) * 2 + 1]) + v3 * __ldg(&W2[(f0 + 3) * 2 + 1]);

    o0 += __shfl_xor_sync(FULL, o0, 1);
    o0 += __shfl_xor_sync(FULL, o0, 2);
    o1 += __shfl_xor_sync(FULL, o1, 1);
    o1 += __shfl_xor_sync(FULL, o1, 2);

    if (lane == 0) {
        float2 wv;
        wv.x = o0 * di;
        wv.y = o1 * di;
        *(float2*)&g_hs2[i * F_OUT] = wv;
    }
}

// Layer-2 aggregate + finalize + log_softmax: 8 lanes per node, tiered.
__global__ void k_agg2(const float* __restrict__ b2, float* __restrict__ out) {
    const unsigned FULL = 0xffffffffu;
    int gid = blockIdx.x * blockDim.x + threadIdx.x;
    int i = gid >> 3;        // grid exact: 100000*8/256 = 3125 blocks
    int sub = gid & 7;

    int deg = g_pos[i] - i * CAP;
    const float2* hs = (const float2*)g_hs2;
    const int* bucket = &g_src[i * CAP];

    float o0 = 0.0f, o1 = 0.0f;

    // tier 0: e = sub..sub+24 (covers deg<=32)
    {
        int idx[4];
#pragma unroll
        for (int it = 0; it < 4; it++) idx[it] = __ldg(&bucket[sub + (it << 3)]);
#pragma unroll
        for (int it = 0; it < 4; it++) {
            int e = sub + (it << 3);
            if (e < deg) {
                float2 v = __ldg(&hs[idx[it]]);
                o0 += v.x; o1 += v.y;
            }
        }
    }
    if (__any_sync(FULL, deg > 32)) {  // warp-uniform tail
        int idx[8];
#pragma unroll
        for (int it = 4; it < 12; it++) idx[it - 4] = __ldg(&bucket[sub + (it << 3)]);
#pragma unroll
        for (int it = 4; it < 12; it++) {
            int e = sub + (it << 3);
            if (e < deg) {
                float2 v = __ldg(&hs[idx[it - 4]]);
                o0 += v.x; o1 += v.y;
            }
        }
    }

    o0 += __shfl_xor_sync(FULL, o0, 1);
    o0 += __shfl_xor_sync(FULL, o0, 2);
    o0 += __shfl_xor_sync(FULL, o0, 4);
    o1 += __shfl_xor_sync(FULL, o1, 1);
    o1 += __shfl_xor_sync(FULL, o1, 2);
    o1 += __shfl_xor_sync(FULL, o1, 4);

    if (sub == 0) {
        float2 self = hs[i];
        float di = g_dinv[i];
        float a0 = (o0 + self.x) * di + __ldg(&b2[0]);
        float a1 = (o1 + self.y) * di + __ldg(&b2[1]);
        float m = fmaxf(a0, a1);
        float lse = m + logf(expf(a0 - m) + expf(a1 - m));
        float2 r2;
        r2.x = a0 - lse;
        r2.y = a1 - lse;
        *(float2*)&out[i * F_OUT] = r2;
    }
}

// ---------------------------------------------------------------------------
extern "C" void kernel_launch(void* const* d_in, const int* in_sizes, int n_in,
                              void* d_out, int out_size) {
    const float* x = (const float*)d_in[0];
    const void* ei = d_in[1];
    const float* W1 = (const float*)d_in[2];
    const float* b1 = (const float*)d_in[3];
    const float* W2 = (const float*)d_in[4];
    const float* b2 = (const float*)d_in[5];
    float* out = (float*)d_out;

    const int TB = 256;
    k_init<<<148, TB>>>((const unsigned int*)ei);
    k_fill<<<(N_EDGES / 8 + TB - 1) / TB, TB>>>(ei);
    k_xform1<<<(N_NODES + TB - 1) / TB, TB>>>(x, W1);
    k_agg1<<<N_NODES * 32 / TB, TB>>>(b1, W2);   // warp per node, exact
    k_agg2<<<N_NODES * 8 / TB, TB>>>(b2, out);   // 8 lanes per node, exact
}

// round 10
// speedup vs baseline: 1.0564x; 1.0437x over previous
#include <cuda_runtime.h>
#include <math.h>

#define N_NODES 100000
#define N_EDGES 3200000
#define F_IN 25
#define F_HID 16
#define F_OUT 2
#define CAP 96   // bucket capacity; deg ~ Poisson(32), P(deg>96) ~ 1e-20

// Scratch (allocation-free rule: __device__ globals).
// g_posrel is RELATIVE cursor (0-based): statically zero-initialized at module
// load; k_agg2 resets it to 0 after last use so every launch sees zeros.
__device__ int   g_posrel[N_NODES];
__device__ int   g_src[N_NODES * CAP];      // source ids bucketed by target
__device__ float g_dinv[N_NODES];
__device__ float g_hs1[N_NODES * F_HID];    // (x@W1) * dinv[i]
__device__ float g_hs2[N_NODES * F_OUT];    // (relu(l1)@W2) * dinv[i]

__device__ __forceinline__ void addx2(unsigned long long& a, unsigned long long v) {
    asm("add.rn.f32x2 %0, %0, %1;" : "+l"(a) : "l"(v));
}
union F2U { unsigned long long u; float2 f; };

// ---------------------------------------------------------------------------
// Bucket fill: 8 edges/thread. Dtype detected per-warp via ballot on the
// first 32 odd 32-bit words (all-zero <=> int64); identical verdict everywhere.
__global__ void k_fill(const void* __restrict__ ei) {
    const unsigned FULL = 0xffffffffu;
    int lane = threadIdx.x & 31;
    unsigned odd = __ldg(&((const unsigned*)ei)[2 * lane + 1]);
    bool is64 = (__ballot_sync(FULL, odd != 0u) == 0u);

    int e0 = 8 * (blockIdx.x * blockDim.x + threadIdx.x);
    if (e0 >= N_EDGES) return;

    int r[8], c[8];
    const int4* w = (const int4*)ei;
    if (is64) {
#pragma unroll
        for (int k = 0; k < 4; k++) {
            int4 a = __ldg(&w[e0 / 2 + k]);
            r[2 * k] = a.x; r[2 * k + 1] = a.z;
        }
        long long cb = (long long)N_EDGES + e0;
#pragma unroll
        for (int k = 0; k < 4; k++) {
            int4 a = __ldg(&w[cb / 2 + k]);
            c[2 * k] = a.x; c[2 * k + 1] = a.z;
        }
    } else {
#pragma unroll
        for (int k = 0; k < 2; k++) {
            int4 a = __ldg(&w[e0 / 4 + k]);
            r[4 * k] = a.x; r[4 * k + 1] = a.y; r[4 * k + 2] = a.z; r[4 * k + 3] = a.w;
        }
#pragma unroll
        for (int k = 0; k < 2; k++) {
            int4 a = __ldg(&w[(N_EDGES + e0) / 4 + k]);
            c[4 * k] = a.x; c[4 * k + 1] = a.y; c[4 * k + 2] = a.z; c[4 * k + 3] = a.w;
        }
    }
    int p[8];
#pragma unroll
    for (int k = 0; k < 8; k++) p[k] = c[k] * CAP + atomicAdd(&g_posrel[c[k]], 1);
#pragma unroll
    for (int k = 0; k < 8; k++) g_src[p[k]] = r[k];
}

// Layer-1 transform fused with dinv: hs1[i] = (x[i] @ W1) * dinv[i].
__global__ void k_xform1(const float* __restrict__ x, const float* __restrict__ W1) {
    __shared__ float sW1[F_IN * F_HID];
    __shared__ float sx[256 * F_IN];
    for (int i = threadIdx.x; i < F_IN * F_HID; i += blockDim.x)
        sW1[i] = W1[i];

    int base_node = blockIdx.x * 256;
    int nvals = min(256, N_NODES - base_node) * F_IN;
    const float* xblk = x + base_node * F_IN;
    for (int j = threadIdx.x; j < nvals; j += blockDim.x)
        sx[j] = xblk[j];
    __syncthreads();

    int i = base_node + threadIdx.x;
    if (i >= N_NODES) return;

    float di = rsqrtf((float)g_posrel[i] + 1.0f);  // +1 self loop
    g_dinv[i] = di;

    const float* xi = &sx[threadIdx.x * F_IN];
    float acc[F_HID];
#pragma unroll
    for (int f = 0; f < F_HID; f++) acc[f] = 0.0f;
#pragma unroll
    for (int k = 0; k < F_IN; k++) {
        float xv = xi[k];
#pragma unroll
        for (int f = 0; f < F_HID; f++) acc[f] += xv * sW1[k * F_HID + f];
    }

    float4* out = (float4*)&g_hs1[i * F_HID];
#pragma unroll
    for (int q = 0; q < 4; q++) {
        float4 v;
        v.x = acc[q * 4 + 0] * di;
        v.y = acc[q * 4 + 1] * di;
        v.z = acc[q * 4 + 2] * di;
        v.w = acc[q * 4 + 3] * di;
        out[q] = v;
    }
}

// Layer-1 aggregate: warp per node, 4 lanes per edge (64B row coalesced),
// packed f32x2 accumulation, 16-edge tiers.
__global__ void k_agg1(const float* __restrict__ b1, const float* __restrict__ W2) {
    const unsigned FULL = 0xffffffffu;
    int i = (blockIdx.x * blockDim.x + threadIdx.x) >> 5;  // node (grid exact)
    int lane = threadIdx.x & 31;
    int q = lane & 3;        // feature quad
    int slot = lane >> 2;    // edge slot 0..7

    int deg = g_posrel[i];
    const float4* hs = (const float4*)g_hs1;
    const int* bucket = &g_src[i * CAP];

    int ia = __ldg(&bucket[lane]);
    unsigned long long acc01 = 0ull, acc23 = 0ull;  // packed {0.0f,0.0f}

#define AGG1_BODY(IT, IDX)                                                   \
    {                                                                        \
        int e = ((IT) << 3) + slot;                                          \
        int r = __shfl_sync(FULL, (IDX), e & 31);                            \
        if (e < deg) {                                                       \
            ulonglong2 v = __ldg((const ulonglong2*)(hs + r * 4 + q));       \
            addx2(acc01, v.x);                                               \
            addx2(acc23, v.y);                                               \
        }                                                                    \
    }

    AGG1_BODY(0, ia) AGG1_BODY(1, ia)
    if (deg > 16) {
        AGG1_BODY(2, ia) AGG1_BODY(3, ia)
        if (deg > 32) {
            int ib = __ldg(&bucket[lane + 32]);
            AGG1_BODY(4, ib) AGG1_BODY(5, ib)
            if (deg > 48) {
                AGG1_BODY(6, ib) AGG1_BODY(7, ib)
                if (deg > 64) {
                    int ic = __ldg(&bucket[lane + 64]);
                    AGG1_BODY(8, ic) AGG1_BODY(9, ic)
                    if (deg > 80) {
                        AGG1_BODY(10, ic) AGG1_BODY(11, ic)
                    }
                }
            }
        }
    }
#undef AGG1_BODY

    // reduce across the 8 slots (packed)
#pragma unroll
    for (int m = 4; m <= 16; m <<= 1) {
        addx2(acc01, __shfl_xor_sync(FULL, acc01, m));
        addx2(acc23, __shfl_xor_sync(FULL, acc23, m));
    }

    F2U u01, u23;
    u01.u = acc01; u23.u = acc23;

    float di = g_dinv[i];
    float4 self = __ldg(&hs[i * 4 + q]);
    float4 bq = __ldg(&((const float4*)b1)[q]);
    float v0 = fmaxf((u01.f.x + self.x) * di + bq.x, 0.0f);
    float v1 = fmaxf((u01.f.y + self.y) * di + bq.y, 0.0f);
    float v2 = fmaxf((u23.f.x + self.z) * di + bq.z, 0.0f);
    float v3 = fmaxf((u23.f.y + self.w) * di + bq.w, 0.0f);

    int f0 = q * 4;
    float o0 = v0 * __ldg(&W2[(f0 + 0) * 2])     + v1 * __ldg(&W2[(f0 + 1) * 2]) +
               v2 * __ldg(&W2[(f0 + 2) * 2])     + v3 * __ldg(&W2[(f0 + 3) * 2]);
    float o1 = v0 * __ldg(&W2[(f0 + 0) * 2 + 1]) + v1 * __ldg(&W2[(f0 + 1) * 2 + 1]) +
               v2 * __ldg(&W2[(f0 + 2) * 2 + 1]) + v3 * __ldg(&W2[(f0 + 3) * 2 + 1]);

    o0 += __shfl_xor_sync(FULL, o0, 1);
    o0 += __shfl_xor_sync(FULL, o0, 2);
    o1 += __shfl_xor_sync(FULL, o1, 1);
    o1 += __shfl_xor_sync(FULL, o1, 2);

    if (lane == 0) {
        float2 wv;
        wv.x = o0 * di;
        wv.y = o1 * di;
        *(float2*)&g_hs2[i * F_OUT] = wv;
    }
}

// Layer-2 aggregate + finalize + log_softmax: 8 lanes/node, packed adds,
// tiered tail. Resets g_posrel for the next launch.
__global__ void k_agg2(const float* __restrict__ b2, float* __restrict__ out) {
    const unsigned FULL = 0xffffffffu;
    int gid = blockIdx.x * blockDim.x + threadIdx.x;
    int i = gid >> 3;        // grid exact: 100000*8/256 = 3125 blocks
    int sub = gid & 7;

    int deg = g_posrel[i];
    const unsigned long long* hs = (const unsigned long long*)g_hs2;
    const int* bucket = &g_src[i * CAP];

    // reset cursor for next launch (deg already read by all consumers)
    if (sub == 0) g_posrel[i] = 0;

    unsigned long long acc = 0ull;

    {   // tier 0: its 0..3 (covers deg<=32)
        int idx[4];
#pragma unroll
        for (int it = 0; it < 4; it++) idx[it] = __ldg(&bucket[sub + (it << 3)]);
#pragma unroll
        for (int it = 0; it < 4; it++) {
            int e = sub + (it << 3);
            if (e < deg) addx2(acc, __ldg(&hs[idx[it]]));
        }
    }
    if (__any_sync(FULL, deg > 32)) {   // tier 1: its 4..7
        int idx[4];
#pragma unroll
        for (int it = 4; it < 8; it++) idx[it - 4] = __ldg(&bucket[sub + (it << 3)]);
#pragma unroll
        for (int it = 4; it < 8; it++) {
            int e = sub + (it << 3);
            if (e < deg) addx2(acc, __ldg(&hs[idx[it - 4]]));
        }
        if (__any_sync(FULL, deg > 64)) {   // tier 2: its 8..11
            int idx[4];
#pragma unroll
            for (int it = 8; it < 12; it++) idx[it - 8] = __ldg(&bucket[sub + (it << 3)]);
#pragma unroll
            for (int it = 8; it < 12; it++) {
                int e = sub + (it << 3);
                if (e < deg) addx2(acc, __ldg(&hs[idx[it - 8]]));
            }
        }
    }

    addx2(acc, __shfl_xor_sync(FULL, acc, 1));
    addx2(acc, __shfl_xor_sync(FULL, acc, 2));
    addx2(acc, __shfl_xor_sync(FULL, acc, 4));

    if (sub == 0) {
        F2U u; u.u = acc;
        F2U s; s.u = hs[i];
        float di = g_dinv[i];
        float a0 = (u.f.x + s.f.x) * di + __ldg(&b2[0]);
        float a1 = (u.f.y + s.f.y) * di + __ldg(&b2[1]);
        float m = fmaxf(a0, a1);
        float lse = m + logf(expf(a0 - m) + expf(a1 - m));
        float2 r2;
        r2.x = a0 - lse;
        r2.y = a1 - lse;
        *(float2*)&out[i * F_OUT] = r2;
    }
}

// ---------------------------------------------------------------------------
extern "C" void kernel_launch(void* const* d_in, const int* in_sizes, int n_in,
                              void* d_out, int out_size) {
    const float* x = (const float*)d_in[0];
    const void* ei = d_in[1];
    const float* W1 = (const float*)d_in[2];
    const float* b1 = (const float*)d_in[3];
    const float* W2 = (const float*)d_in[4];
    const float* b2 = (const float*)d_in[5];
    float* out = (float*)d_out;

    const int TB = 256;
    k_fill<<<(N_EDGES / 8 + TB - 1) / TB, TB>>>(ei);
    k_xform1<<<(N_NODES + TB - 1) / TB, TB>>>(x, W1);
    k_agg1<<<N_NODES * 32 / TB, TB>>>(b1, W2);   // warp per node, exact
    k_agg2<<<N_NODES * 8 / TB, TB>>>(b2, out);   // 8 lanes per node, exact
}